// round 6
// baseline (speedup 1.0000x reference)
#include <cuda_runtime.h>
#include <cstdint>

// Problem constants (fixed-shape instance)
#define BB 16
#define CC 192
#define HH 224
#define WW 224
#define SS 196

#define ROWCHUNKS 16
#define ROWS_PER (HH / ROWCHUNKS)     // 14
#define PIX (ROWS_PER * WW)           // 3136
#define PLANE_BYTES (PIX * 4)         // 12544 (contiguous per channel per chunk)

#define NC 4                          // channels per group
#define NGROUPS (CC / NC)             // 48
#define NSTAGE 3                      // pipeline depth
#define STRIDE 3144                   // padded plane stride (floats); %32==8
#define GROUP_BYTES (NC * PLANE_BYTES) // 50176
#define NTH 512
#define NGATHER (SS * 2)              // 392 gather threads: (segment, channel-pair)

// dyn smem (floats): ring[NSTAGE*NC*STRIDE] | sorted[PIX] | hist[SS] | scanbuf[NTH] | mbars
#define RING_FLOATS (NSTAGE * NC * STRIDE)
#define SMEM_FLOATS (RING_FLOATS + PIX + SS + NTH)
#define SMEM_BYTES (SMEM_FLOATS * 4 + 64)

__device__ float g_counts[BB * SS];

__device__ __forceinline__ uint32_t smem_u32(const void* p) {
    uint32_t a;
    asm("{ .reg .u64 t; cvta.to.shared.u64 t, %1; cvt.u32.u64 %0, t; }" : "=r"(a) : "l"(p));
    return a;
}
__device__ __forceinline__ void mbar_init(uint32_t mbar, uint32_t cnt) {
    asm volatile("mbarrier.init.shared.b64 [%0], %1;" :: "r"(mbar), "r"(cnt) : "memory");
}
__device__ __forceinline__ void mbar_expect_tx(uint32_t mbar, uint32_t bytes) {
    asm volatile("mbarrier.arrive.expect_tx.shared.b64 _, [%0], %1;" :: "r"(mbar), "r"(bytes) : "memory");
}
__device__ __forceinline__ void mbar_wait(uint32_t mbar, uint32_t parity) {
    asm volatile(
        "{\n\t"
        ".reg .pred P;\n\t"
        "W_%=:\n\t"
        "mbarrier.try_wait.parity.acquire.cta.shared::cta.b64 P, [%0], %1, 0x989680;\n\t"
        "@P bra D_%=;\n\t"
        "bra W_%=;\n\t"
        "D_%=:\n\t"
        "}" :: "r"(mbar), "r"(parity) : "memory");
}
__device__ __forceinline__ void bulk_g2s(uint32_t dst, const void* src, uint32_t bytes, uint32_t mbar) {
    asm volatile("cp.async.bulk.shared::cta.global.mbarrier::complete_tx::bytes [%0], [%1], %2, [%3];"
                 :: "r"(dst), "l"(src), "r"(bytes), "r"(mbar) : "memory");
}

// ---------------- Kernel 1: zero sums (d_out) and counts ----------------
__global__ void zero_kernel(float* __restrict__ out) {
    const int n = BB * SS * CC;
    int idx = blockIdx.x * blockDim.x + threadIdx.x;
    int stride = gridDim.x * blockDim.x;
    for (int i = idx; i < n; i += stride) out[i] = 0.0f;
    for (int i = idx; i < BB * SS; i += stride) g_counts[i] = 0.0f;
}

// ---------------- Kernel 2: sort once + TMA-pipelined, segment-aligned reduction ----------------
// grid: (ROWCHUNKS, 1, BB), block: 512
__global__ __launch_bounds__(NTH) void accum_kernel(
    const float* __restrict__ feat,   // (B, C, H, W) fp32
    const int* __restrict__ seg,      // (B, H, W) int32
    float* __restrict__ out)          // (B, S, C) fp32 (sums)
{
    extern __shared__ char smem_raw[];
    float* ring    = (float*)smem_raw;               // NSTAGE * NC * STRIDE
    int*   sorted  = (int*)(ring + RING_FLOATS);     // PIX (pixel idx, segment-sorted)
    int*   hist    = sorted + PIX;                   // SS (post-scatter: end offsets)
    int*   scanbuf = hist + SS;                      // NTH
    unsigned long long* mbars = (unsigned long long*)(scanbuf + NTH);  // NSTAGE

    const int tid = threadIdx.x;
    const int b   = blockIdx.z;
    const int h0  = blockIdx.x * ROWS_PER;

    const uint32_t mbar0 = smem_u32(mbars);

    if (tid == 0) {
        #pragma unroll
        for (int s = 0; s < NSTAGE; ++s) mbar_init(mbar0 + 8 * s, 1);
    }

    // ================= Phase 1: counting sort by segment id (once per chunk) =================
    int* segtmp = (int*)ring;  // scratch (ring unused yet), PIX ints

    for (int i = tid; i < SS; i += NTH) hist[i] = 0;
    __syncthreads();

    const int* segbase = seg + ((size_t)b * HH + h0) * WW;   // contiguous PIX ints
    for (int i = tid; i < PIX; i += NTH) {
        int s = segbase[i];
        s = min(max(s, 0), SS - 1);
        segtmp[i] = s;
        atomicAdd(&hist[s], 1);
    }
    __syncthreads();

    // counts (each CTA owns a unique (b, rowchunk))
    for (int i = tid; i < SS; i += NTH)
        atomicAdd(&g_counts[b * SS + i], (float)hist[i]);

    // block-wide exclusive scan of hist (SS <= NTH)
    int v = (tid < SS) ? hist[tid] : 0;
    scanbuf[tid] = v;
    __syncthreads();
    #pragma unroll
    for (int d = 1; d < NTH; d <<= 1) {
        int t = (tid >= d) ? scanbuf[tid - d] : 0;
        __syncthreads();
        scanbuf[tid] += t;
        __syncthreads();
    }
    if (tid < SS) hist[tid] = scanbuf[tid] - v;  // exclusive start offsets
    __syncthreads();

    // scatter: sorted[pos] = local pixel idx; afterwards hist[s] = end offset of segment s
    for (int i = tid; i < PIX; i += NTH) {
        int s = segtmp[i];
        int pos = atomicAdd(&hist[s], 1);
        sorted[pos] = i;
    }
    __syncthreads();   // sort done; ring scratch dead -> safe for TMA

    // ================= Phase 2: pipelined channel groups =================
    const float* featbase = feat + ((size_t)b * CC * HH + h0) * WW;  // + c*HH*WW
    const size_t plane = (size_t)HH * WW;
    const uint32_t ring_s = smem_u32(ring);

    // prologue: issue TMAs for groups 0..NSTAGE-1
    if (tid == 0) {
        #pragma unroll
        for (int s = 0; s < NSTAGE; ++s) {
            mbar_expect_tx(mbar0 + 8 * s, GROUP_BYTES);
            #pragma unroll
            for (int c = 0; c < NC; ++c) {
                bulk_g2s(ring_s + (uint32_t)((s * NC + c) * STRIDE) * 4,
                         featbase + (size_t)(s * NC + c) * plane,
                         PLANE_BYTES, mbar0 + 8 * s);
            }
        }
    }

    // segment-aligned decomposition: thread t<392 -> segment t>>1, channel pair t&1
    const int sseg = tid >> 1;
    const int cp   = tid & 1;
    int wst = 0, wen = 0;
    if (tid < NGATHER) {
        wen = hist[sseg];
        wst = (sseg == 0) ? 0 : hist[sseg - 1];
    }

    float* obase0 = out + (size_t)b * SS * CC + (size_t)sseg * CC + 2 * cp;

    for (int g = 0; g < NGROUPS; ++g) {
        const int st = g % NSTAGE;
        const uint32_t mb = mbar0 + 8 * st;
        mbar_wait(mb, (g / NSTAGE) & 1);

        float a0 = 0.f, a1 = 0.f;
        if (tid < NGATHER) {
            const float* p0 = ring + (st * NC + 2 * cp + 0) * STRIDE;
            const float* p1 = ring + (st * NC + 2 * cp + 1) * STRIDE;
            #pragma unroll 4
            for (int i = wst; i < wen; ++i) {
                int idx = sorted[i];
                a0 += p0[idx];
                a1 += p1[idx];
            }
        }

        __syncthreads();   // all gathers on buffer st complete before refill

        if (tid == 0 && g + NSTAGE < NGROUPS) {
            const int gn = g + NSTAGE;
            mbar_expect_tx(mb, GROUP_BYTES);
            #pragma unroll
            for (int c = 0; c < NC; ++c) {
                bulk_g2s(ring_s + (uint32_t)((st * NC + c) * STRIDE) * 4,
                         featbase + (size_t)(gn * NC + c) * plane,
                         PLANE_BYTES, mb);
            }
        }

        // flush after ring release: REDG overlaps next TMA fill
        if (tid < NGATHER && wen > wst) {
            float* oaddr = obase0 + g * NC;
            asm volatile("red.global.add.v2.f32 [%0], {%1,%2};"
                         :: "l"(oaddr), "f"(a0), "f"(a1) : "memory");
        }
    }
}

// ---------------- Kernel 3: finalize (divide by count, add positional embedding) ----------------
__global__ void finalize_kernel(
    float* __restrict__ out,                   // (B, S, C) sums -> final
    const float* __restrict__ centroid,        // (B, S, 2)
    const float* __restrict__ posW,            // (2, C)
    const float* __restrict__ posb)            // (C,)
{
    int idx = blockIdx.x * blockDim.x + threadIdx.x;
    if (idx >= BB * SS * CC) return;
    int c  = idx % CC;
    int bs = idx / CC;
    float cnt = g_counts[bs];
    float cx = centroid[bs * 2 + 0] * (1.0f / WW);
    float cy = centroid[bs * 2 + 1] * (1.0f / HH);
    float pos = fmaf(cx, posW[c], fmaf(cy, posW[CC + c], posb[c]));
    out[idx] = out[idx] / fmaxf(cnt, 1.0f) + pos;
}

extern "C" void kernel_launch(void* const* d_in, const int* in_sizes, int n_in,
                              void* d_out, int out_size)
{
    // inputs: 0=img(unused) 1=features 2=segments(int32) 3=centroid_coords 4=pos_W 5=pos_b 6=max_segments
    const float* feat     = (const float*)d_in[1];
    const int*   seg      = (const int*)d_in[2];
    const float* centroid = (const float*)d_in[3];
    const float* posW     = (const float*)d_in[4];
    const float* posb     = (const float*)d_in[5];
    float* out = (float*)d_out;

    (void)in_sizes; (void)n_in; (void)out_size;

    static bool attr_set = false;
    if (!attr_set) {
        cudaFuncSetAttribute(accum_kernel,
                             cudaFuncAttributeMaxDynamicSharedMemorySize, SMEM_BYTES);
        attr_set = true;
    }

    zero_kernel<<<1024, 256>>>(out);

    dim3 grid(ROWCHUNKS, 1, BB);
    accum_kernel<<<grid, NTH, SMEM_BYTES>>>(feat, seg, out);

    int n = BB * SS * CC;
    finalize_kernel<<<(n + 255) / 256, 256>>>(out, centroid, posW, posb);
}